// round 2
// baseline (speedup 1.0000x reference)
#include <cuda_runtime.h>

// Problem constants (fixed by the dataset: B=1, L=520, V=32128, r=512, leniency=2)
#define VOCAB     32128
#define RIDX      512
#define KROWS     8          // K = L - r
#define STAT_ROWS 9          // rows 511..519 need softmax stats / argmax
#define HEAD      521        // id_res length = r + K + 1
// output layout: [ id_res(521) | prob_res(520*32128) | n_match(1) ], all float32
#define NMATCH_OFF ((size_t)HEAD + (size_t)520 * VOCAB)

// Scratch (no allocations allowed -> __device__ globals)
__device__ float g_max[STAT_ROWS];
__device__ float g_sum[STAT_ROWS];
__device__ int   g_amax[STAT_ROWS];
__device__ int   g_nmatch;

// input_ids may arrive as int32 or int64 (JAX x64 ambiguity). Values are
// < 32768, so for little-endian int64 every odd 32-bit word is 0. Probing 16
// odd words is a deterministic discriminator (16 consecutive zeros at odd
// positions is effectively impossible for random ids in [0,32128) as int32).
__device__ __forceinline__ bool ids_is_i64(const int* p) {
    #pragma unroll
    for (int i = 0; i < 16; i++)
        if (p[2 * i + 1] != 0) return false;
    return true;
}
__device__ __forceinline__ int get_id(const int* p, int i, bool is64) {
    return is64 ? p[2 * i] : p[i];
}

// ---------------------------------------------------------------------------
// Kernel 1: single-pass online-softmax stats (max, sumexp, argmax) for rows
// 511..519 of target_logits. 9 blocks x 1024 threads; each thread touches 32
// elements -> deep MLP, one DRAM pass per row (1.1 MB total).
// ---------------------------------------------------------------------------
__global__ void __launch_bounds__(1024) stats_kernel(const float* __restrict__ logits) {
    const int j   = blockIdx.x;                 // 0..8  -> global row 511+j
    const int tid = threadIdx.x;
    const float* row = logits + (size_t)(RIDX - 1 + j) * VOCAB;

    // Thread-local online softmax + argmax. m tracks the running max value,
    // am its first index, d the sum of exp rescaled to the current m.
    float m = -3.4e38f, d = 0.0f;
    int   am = 0;
    for (int i = tid; i < VOCAB; i += 1024) {
        float x = row[i];
        if (x > m) {                 // strict > keeps first occurrence
            d = d * __expf(0.0f);    // no-op, keep structure simple
            d = d * expf(m - x);     // rescale old sum to new max
            m = x; am = i;
            d += 1.0f;               // exp(x - x) = 1
        } else {
            d += expf(x - m);
        }
    }

    __shared__ float sm[1024];
    __shared__ float sd[1024];
    __shared__ int   si[1024];
    sm[tid] = m; sd[tid] = d; si[tid] = am;
    __syncthreads();

    // Tree-combine (m,d,idx) pairs.
    for (int s = 512; s > 0; s >>= 1) {
        if (tid < s) {
            float m1 = sm[tid],     d1 = sd[tid];     int i1 = si[tid];
            float m2 = sm[tid + s], d2 = sd[tid + s]; int i2 = si[tid + s];
            float M = fmaxf(m1, m2);
            float D = d1 * expf(m1 - M) + d2 * expf(m2 - M);
            int   I;
            if      (m2 > m1) I = i2;
            else if (m1 > m2) I = i1;
            else              I = min(i1, i2);   // tie -> first occurrence
            sm[tid] = M; sd[tid] = D; si[tid] = I;
        }
        __syncthreads();
    }

    if (tid == 0) {
        g_max[j]  = sm[0];
        g_sum[j]  = sd[0];
        g_amax[j] = si[0];
    }
}

// ---------------------------------------------------------------------------
// Kernel 2: acceptance decision + id_res head/tail + n_match scalar.
// 1 block x 512 threads (head copy is parallel; the scan is 1 thread, 8 terms).
// ---------------------------------------------------------------------------
__global__ void decide_kernel(const float* __restrict__ logits,
                              const float* __restrict__ probs,
                              const int*   __restrict__ ids,
                              float*       __restrict__ out) {
    const int  tid  = threadIdx.x;
    const bool is64 = ids_is_i64(ids);

    // id_res[0:512] = input_ids[0:512]
    for (int i = tid; i < RIDX; i += blockDim.x)
        out[i] = (float)get_id(ids, i, is64);

    if (tid == 0) {
        // prefix-accept scan over the 8 speculated tokens
        int  n  = 0;
        bool on = true;
        #pragma unroll
        for (int k = 0; k < KROWS; k++) {
            const int draft = get_id(ids, RIDX + k, is64);   // input_ids[512+k]
            const int tgt   = g_amax[k];                     // argmax of row 511+k
            const size_t off = (size_t)(RIDX - 1 + k) * VOCAB + draft;
            const float tp = expf(logits[off] - g_max[k]) / g_sum[k];
            const float pp = probs[off];
            const bool accept = (tgt == draft) || (tp > pp * 0.5f);  // leniency=2
            if (on && accept) n++; else on = false;
        }
        g_nmatch = n;

        // new_ids[pos], pos = 0..8  ->  id_res[512..520]
        #pragma unroll
        for (int pos = 0; pos <= KROWS; pos++) {
            float v;
            if      (pos <  n) v = (float)get_id(ids, RIDX + pos, is64);
            else if (pos == n) v = (float)g_amax[pos];       // target_ids[pos]
            else               v = 0.0f;
            out[RIDX + pos] = v;
        }
        out[NMATCH_OFF] = (float)n;
    }
}

// ---------------------------------------------------------------------------
// Kernel 3: prob_res rows 512..519 = (k < n_match) ? softmax(logits row 511+k) : 0
// grid = (126, 8) x 256 threads. ~1.2 MB traffic; logits rows are L2-hot
// from the stats pass.
// ---------------------------------------------------------------------------
__global__ void tail_kernel(const float* __restrict__ logits,
                            float*       __restrict__ out) {
    const int k   = blockIdx.y;                       // 0..7
    const int col = blockIdx.x * blockDim.x + threadIdx.x;
    if (col >= VOCAB) return;

    float v = 0.0f;
    if (k < g_nmatch) {
        const size_t off = (size_t)(RIDX - 1 + k) * VOCAB + col;
        v = expf(logits[off] - g_max[k]) * (1.0f / g_sum[k]);
    }
    out[(size_t)HEAD + (size_t)(RIDX + k) * VOCAB + col] = v;
}

// ---------------------------------------------------------------------------
extern "C" void kernel_launch(void* const* d_in, const int* in_sizes, int n_in,
                              void* d_out, int out_size) {
    const float* logits = (const float*)d_in[0];   // target_logits (1,520,32128) f32
    const float* probs  = (const float*)d_in[1];   // probs         (1,520,32128) f32
    const int*   ids    = (const int*)d_in[2];     // input_ids     (1,520) i32/i64
    float*       out    = (float*)d_out;

    stats_kernel<<<STAT_ROWS, 1024>>>(logits);
    decide_kernel<<<1, 512>>>(logits, probs, ids, out);

    // prob_res rows 0..511: verbatim copy of probs (65.8 MB) — the HBM-bound bulk.
    cudaMemcpyAsync(out + HEAD, probs, (size_t)RIDX * VOCAB * sizeof(float),
                    cudaMemcpyDeviceToDevice, 0);

    dim3 grid((VOCAB + 255) / 256, KROWS);
    tail_kernel<<<grid, 256>>>(logits, out);
}

// round 4
// speedup vs baseline: 1.9983x; 1.9983x over previous
#include <cuda_runtime.h>

// Problem constants (fixed by dataset: B=1, L=520, V=32128, r=512, leniency=2)
#define VOCAB     32128
#define RIDX      512
#define KROWS     8
#define STAT_ROWS 9          // rows 511..519 need softmax stats / argmax
#define HEAD      521        // id_res length = r + K + 1
#define NMATCH_OFF ((size_t)HEAD + (size_t)520 * VOCAB)

// Bulk copy geometry: prob_res[0:512] = probs[0:512] (16,449,536 floats).
// Peel 3 floats so the vector dst (out + 524) is 16B-aligned.
#define COPY_FLOATS ((size_t)RIDX * VOCAB)          // 16,449,536
#define NV4         ((COPY_FLOATS - 3) / 4)         // 4,112,383 float4 stores
#define COPY_BLOCKS 287                             // + 9 stats blocks = 296 = 2/SM

__device__ float g_max[STAT_ROWS];
__device__ float g_sum[STAT_ROWS];
__device__ int   g_amax[STAT_ROWS];
__device__ int   g_nmatch;

// input_ids may be int32 or int64 (JAX x64 ambiguity). Values < 32768, so for
// little-endian int64 every odd 32-bit word is 0; 16 consecutive zero odd
// words is a deterministic discriminator against the int32 interpretation.
__device__ __forceinline__ bool ids_is_i64(const int* p) {
    #pragma unroll
    for (int i = 0; i < 16; i++)
        if (p[2 * i + 1] != 0) return false;
    return true;
}
__device__ __forceinline__ int get_id(const int* p, int i, bool is64) {
    return is64 ? p[2 * i] : p[i];
}

// ---------------------------------------------------------------------------
// Fused kernel: blocks 0..8 compute softmax stats for logits rows 511..519
// (latency-bound, 9 SMs); blocks 9..295 stream the 65.8 MB probs copy
// (DRAM-bound). Stats hide entirely under the copy.
// ---------------------------------------------------------------------------
__global__ void __launch_bounds__(1024)
fused_stats_copy(const float* __restrict__ logits,
                 const float* __restrict__ probs,
                 float*       __restrict__ out) {
    __shared__ float s_m[32];
    __shared__ int   s_i[32];
    __shared__ float s_d[32];
    __shared__ float s_bM;

    if (blockIdx.x < STAT_ROWS) {
        // ---------------- stats: two-pass, __expf, warp-shuffle reductions
        const int j    = blockIdx.x;
        const int tid  = threadIdx.x;
        const int lane = tid & 31;
        const int warp = tid >> 5;
        const float* row = logits + (size_t)(RIDX - 1 + j) * VOCAB;

        // Pass 1: max + first-occurrence argmax. 4-way unrolled for ILP.
        float m0 = -3.4e38f, m1 = -3.4e38f, m2 = -3.4e38f, m3 = -3.4e38f;
        int   a0 = 0, a1 = 0, a2 = 0, a3 = 0;
        int i = tid;
        for (; i + 3 * 1024 < VOCAB; i += 4 * 1024) {
            float x0 = row[i], x1 = row[i + 1024], x2 = row[i + 2048], x3 = row[i + 3072];
            if (x0 > m0) { m0 = x0; a0 = i; }
            if (x1 > m1) { m1 = x1; a1 = i + 1024; }
            if (x2 > m2) { m2 = x2; a2 = i + 2048; }
            if (x3 > m3) { m3 = x3; a3 = i + 3072; }
        }
        for (; i < VOCAB; i += 1024) {
            float x = row[i];
            if (x > m0) { m0 = x; a0 = i; }
        }
        // combine 4 accumulators (tie -> smallest index)
        float m = m0; int am = a0;
        if (m1 > m || (m1 == m && a1 < am)) { m = m1; am = a1; }
        if (m2 > m || (m2 == m && a2 < am)) { m = m2; am = a2; }
        if (m3 > m || (m3 == m && a3 < am)) { m = m3; am = a3; }

        // warp reduce
        #pragma unroll
        for (int off = 16; off > 0; off >>= 1) {
            float om = __shfl_down_sync(0xffffffffu, m, off);
            int   oa = __shfl_down_sync(0xffffffffu, am, off);
            if (om > m || (om == m && oa < am)) { m = om; am = oa; }
        }
        if (lane == 0) { s_m[warp] = m; s_i[warp] = am; }
        __syncthreads();
        if (warp == 0) {
            m  = s_m[lane]; am = s_i[lane];
            #pragma unroll
            for (int off = 16; off > 0; off >>= 1) {
                float om = __shfl_down_sync(0xffffffffu, m, off);
                int   oa = __shfl_down_sync(0xffffffffu, am, off);
                if (om > m || (om == m && oa < am)) { m = om; am = oa; }
            }
            if (lane == 0) { s_bM = m; g_max[j] = m; g_amax[j] = am; }
        }
        __syncthreads();
        const float M = s_bM;

        // Pass 2: sum of exp(x - M). Row is L2-hot from pass 1.
        float d0 = 0.f, d1 = 0.f, d2 = 0.f, d3 = 0.f;
        i = tid;
        for (; i + 3 * 1024 < VOCAB; i += 4 * 1024) {
            d0 += __expf(row[i]        - M);
            d1 += __expf(row[i + 1024] - M);
            d2 += __expf(row[i + 2048] - M);
            d3 += __expf(row[i + 3072] - M);
        }
        for (; i < VOCAB; i += 1024)
            d0 += __expf(row[i] - M);
        float d = (d0 + d1) + (d2 + d3);
        #pragma unroll
        for (int off = 16; off > 0; off >>= 1)
            d += __shfl_down_sync(0xffffffffu, d, off);
        if (lane == 0) s_d[warp] = d;
        __syncthreads();
        if (warp == 0) {
            d = s_d[lane];
            #pragma unroll
            for (int off = 16; off > 0; off >>= 1)
                d += __shfl_down_sync(0xffffffffu, d, off);
            if (lane == 0) g_sum[j] = d;
        }
    } else {
        // ---------------- bulk copy: prob_res rows 0..511 = probs rows 0..511
        const long long bid = blockIdx.x - STAT_ROWS;
        const long long t0  = bid * 1024 + threadIdx.x;
        const long long nthr = (long long)COPY_BLOCKS * 1024;
        const float*  src  = probs + 3;                            // read side off by 12B
        float4*       dst4 = reinterpret_cast<float4*>(out + HEAD + 3);  // 16B-aligned

        for (long long v = t0; v < (long long)NV4; v += nthr) {
            const float* s = src + 4 * v;
            float4 q;
            q.x = s[0]; q.y = s[1]; q.z = s[2]; q.w = s[3];
            dst4[v] = q;                                           // STG.128
        }
        if (bid == 0 && threadIdx.x == 0) {
            out[HEAD + 0] = probs[0];                              // peeled head
            out[HEAD + 1] = probs[1];
            out[HEAD + 2] = probs[2];
            out[HEAD + COPY_FLOATS - 1] = probs[COPY_FLOATS - 1];  // peeled tail
        }
    }
}

// ---------------------------------------------------------------------------
// Kernel 2: acceptance scan + id_res + n_match (needs stats).
// ---------------------------------------------------------------------------
__global__ void decide_kernel(const float* __restrict__ logits,
                              const float* __restrict__ probs,
                              const int*   __restrict__ ids,
                              float*       __restrict__ out) {
    const int  tid  = threadIdx.x;
    const bool is64 = ids_is_i64(ids);

    for (int i = tid; i < RIDX; i += blockDim.x)
        out[i] = (float)get_id(ids, i, is64);

    if (tid == 0) {
        int  n  = 0;
        bool on = true;
        #pragma unroll
        for (int k = 0; k < KROWS; k++) {
            const int draft = get_id(ids, RIDX + k, is64);
            const int tgt   = g_amax[k];
            const size_t off = (size_t)(RIDX - 1 + k) * VOCAB + draft;
            const float tp = expf(logits[off] - g_max[k]) / g_sum[k]; // precise here
            const float pp = probs[off];
            const bool accept = (tgt == draft) || (tp > pp * 0.5f);   // leniency=2
            if (on && accept) n++; else on = false;
        }
        g_nmatch = n;

        #pragma unroll
        for (int pos = 0; pos <= KROWS; pos++) {
            float v;
            if      (pos <  n) v = (float)get_id(ids, RIDX + pos, is64);
            else if (pos == n) v = (float)g_amax[pos];
            else               v = 0.0f;
            out[RIDX + pos] = v;
        }
        out[NMATCH_OFF] = (float)n;
    }
}

// ---------------------------------------------------------------------------
// Kernel 3: prob_res rows 512..519 (gated by n_match). ~1.2 MB, L2-hot.
// ---------------------------------------------------------------------------
__global__ void tail_kernel(const float* __restrict__ logits,
                            float*       __restrict__ out) {
    const int k   = blockIdx.y;
    const int col = blockIdx.x * blockDim.x + threadIdx.x;
    if (col >= VOCAB) return;

    float v = 0.0f;
    if (k < g_nmatch) {
        const size_t off = (size_t)(RIDX - 1 + k) * VOCAB + col;
        v = __expf(logits[off] - g_max[k]) * (1.0f / g_sum[k]);
    }
    out[(size_t)HEAD + (size_t)(RIDX + k) * VOCAB + col] = v;
}

// ---------------------------------------------------------------------------
extern "C" void kernel_launch(void* const* d_in, const int* in_sizes, int n_in,
                              void* d_out, int out_size) {
    const float* logits = (const float*)d_in[0];
    const float* probs  = (const float*)d_in[1];
    const int*   ids    = (const int*)d_in[2];
    float*       out    = (float*)d_out;

    fused_stats_copy<<<STAT_ROWS + COPY_BLOCKS, 1024>>>(logits, probs, out);
    decide_kernel<<<1, 128>>>(logits, probs, ids, out);
    dim3 grid((VOCAB + 255) / 256, KROWS);
    tail_kernel<<<grid, 256>>>(logits, out);
}